// round 3
// baseline (speedup 1.0000x reference)
#include <cuda_runtime.h>
#include <cuda_bf16.h>
#include <cstdint>

// Problem constants (fixed shapes for Chowder_17188459119037)
#define BB     16
#define NN     8000
#define DD     2048
#define HH     128
#define MROWS  (BB * NN)        // 128000
#define TM     64               // rows per block
#define KT     16               // k-tile
#define NTOP   100
#define NBOT   100
#define NEXT   (NTOP + NBOT)    // 200

__device__ float g_scores[MROWS];
__device__ float g_extreme[BB * NEXT];
__device__ int   g_mask_mode;   // 0=int32, 1=uint8, 2=float32

__device__ __forceinline__ float neg_inf() { return __int_as_float(0xff800000); }

// TF32 rounding (tensor-core input conversion, matches XLA/cuBLAS TF32 GEMM)
__device__ __forceinline__ float tf32r(float x) {
    unsigned r;
    asm("cvt.rna.tf32.f32 %0, %1;" : "=r"(r) : "f"(x));
    return __uint_as_float(r);
}

// ---- packed f32x2 helpers (Blackwell FFMA2) ----
__device__ __forceinline__ unsigned long long pack2(float x, float y) {
    unsigned long long r;
    asm("mov.b64 %0, {%1, %2};" : "=l"(r) : "f"(x), "f"(y));
    return r;
}
__device__ __forceinline__ void unpack2(unsigned long long v, float& x, float& y) {
    asm("mov.b64 {%0, %1}, %2;" : "=f"(x), "=f"(y) : "l"(v));
}
__device__ __forceinline__ void fma2(unsigned long long& d, unsigned long long a,
                                     unsigned long long b) {
    asm("fma.rn.f32x2 %0, %1, %2, %0;" : "+l"(d) : "l"(a), "l"(b));
}

__device__ __forceinline__ float sigmoidf_fast(float x) {
    return 1.0f / (1.0f + __expf(-x));
}

__device__ __forceinline__ bool read_mask(const void* mask, long r, int mode) {
    if (mode == 1) return ((const unsigned char*)mask)[r] != 0;
    if (mode == 0) return ((const int*)mask)[r] != 0;
    return ((const float*)mask)[r] != 0.0f;
}

// ============================================================================
// Kernel 0: detect mask dtype. Scans first 32000 dwords (in-bounds for
// uint8 [32000 dw], int32 [128000 dw], float32 [128000 dw] interpretations).
//   - any dword == 0x3F800000 (1.0f)            -> float32
//   - else any dword > 1 (packed 0/1 bytes)     -> uint8
//   - else (all dwords in {0,1})                -> int32
// ============================================================================
__global__ void detect_mask_kernel(const unsigned* __restrict__ m) {
    __shared__ int s_f32, s_u8;
    if (threadIdx.x == 0) { s_f32 = 0; s_u8 = 0; }
    __syncthreads();
    int f32 = 0, u8 = 0;
    for (int i = threadIdx.x; i < 32000; i += 256) {
        unsigned v = m[i];
        if (v == 0x3F800000u) f32 = 1;
        else if (v > 1u)      u8 = 1;
    }
    if (f32) s_f32 = 1;   // benign race: all writers store 1
    if (u8)  s_u8 = 1;
    __syncthreads();
    if (threadIdx.x == 0) g_mask_mode = s_f32 ? 2 : (s_u8 ? 1 : 0);
}

// ============================================================================
// Kernel 1: fused scores = (sigmoid(F @ W1 + b1) @ W2 + b2), masked -> -inf
// F@W1 operands rounded to TF32 (reference: XLA TF32 GEMM). W2 stage fp32
// (XLA fuses o=1 einsum as a reduce). Block: 256 thr, TM=64 x HH=128.
// ============================================================================
__global__ __launch_bounds__(256) void score_kernel(
    const float* __restrict__ F,   // [MROWS, DD]
    const float* __restrict__ W1,  // [DD, HH]
    const float* __restrict__ b1,  // [HH]
    const float* __restrict__ W2,  // [HH]
    const float* __restrict__ b2,  // [1]
    const void*  __restrict__ mask)  // [MROWS], dtype per g_mask_mode
{
    __shared__ float As[KT][TM + 2];  // padded: conflict-free
    __shared__ float Bs[KT][HH];

    const int tid  = threadIdx.x;
    const int lane = tid & 31;
    const int warp = tid >> 5;           // 0..7 -> row group (8 rows each)
    const long row0 = (long)blockIdx.x * TM;

    const int ar = tid >> 2;             // 0..63 row within tile
    const int ak = (tid & 3) * 4;        // k offset within k-tile
    const float* Aptr = F + (row0 + ar) * (long)DD + ak;

    const float4* Bgl = (const float4*)W1;

    float4 a_reg  = *(const float4*)(Aptr);
    float4 b_reg0 = Bgl[tid];
    float4 b_reg1 = Bgl[tid + 256];

    unsigned long long acc[4][4];
#pragma unroll
    for (int p = 0; p < 4; p++)
#pragma unroll
        for (int c = 0; c < 4; c++) acc[p][c] = 0ull;

    for (int k0 = 0; k0 < DD; k0 += KT) {
        // stage current tile to smem with TF32 input rounding
        As[ak + 0][ar] = tf32r(a_reg.x);
        As[ak + 1][ar] = tf32r(a_reg.y);
        As[ak + 2][ar] = tf32r(a_reg.z);
        As[ak + 3][ar] = tf32r(a_reg.w);
        float4 t0 = make_float4(tf32r(b_reg0.x), tf32r(b_reg0.y),
                                tf32r(b_reg0.z), tf32r(b_reg0.w));
        float4 t1 = make_float4(tf32r(b_reg1.x), tf32r(b_reg1.y),
                                tf32r(b_reg1.z), tf32r(b_reg1.w));
        ((float4*)Bs)[tid]       = t0;
        ((float4*)Bs)[tid + 256] = t1;
        __syncthreads();

        // prefetch next tile (overlaps compute)
        if (k0 + KT < DD) {
            a_reg  = *(const float4*)(Aptr + k0 + KT);
            b_reg0 = Bgl[(size_t)(k0 + KT) * (HH / 4) + tid];
            b_reg1 = Bgl[(size_t)(k0 + KT) * (HH / 4) + tid + 256];
        }

#pragma unroll
        for (int kk = 0; kk < KT; kk++) {
            const float2* Ap = (const float2*)&As[kk][warp * 8];
            float4 bv = *(const float4*)&Bs[kk][lane * 4];
            unsigned long long bd0 = pack2(bv.x, bv.x);
            unsigned long long bd1 = pack2(bv.y, bv.y);
            unsigned long long bd2 = pack2(bv.z, bv.z);
            unsigned long long bd3 = pack2(bv.w, bv.w);
#pragma unroll
            for (int p = 0; p < 4; p++) {
                float2 a2 = Ap[p];
                unsigned long long ad = pack2(a2.x, a2.y);
                fma2(acc[p][0], ad, bd0);
                fma2(acc[p][1], ad, bd1);
                fma2(acc[p][2], ad, bd2);
                fma2(acc[p][3], ad, bd3);
            }
        }
        __syncthreads();
    }

    // Epilogue: bias + sigmoid + fp32 dot with W2 (warp reduce)
    float4 w2v = *(const float4*)(W2 + lane * 4);
    float4 b1v = *(const float4*)(b1 + lane * 4);
    float b2s = b2[0];
    float w2a[4] = {w2v.x, w2v.y, w2v.z, w2v.w};
    float b1a[4] = {b1v.x, b1v.y, b1v.z, b1v.w};
    const int mmode = g_mask_mode;

#pragma unroll
    for (int p = 0; p < 4; p++) {
        float slo = 0.f, shi = 0.f;
#pragma unroll
        for (int c = 0; c < 4; c++) {
            float lo, hi;
            unpack2(acc[p][c], lo, hi);
            slo += w2a[c] * sigmoidf_fast(lo + b1a[c]);
            shi += w2a[c] * sigmoidf_fast(hi + b1a[c]);
        }
#pragma unroll
        for (int o = 16; o > 0; o >>= 1) {
            slo += __shfl_xor_sync(0xffffffffu, slo, o);
            shi += __shfl_xor_sync(0xffffffffu, shi, o);
        }
        if (lane == 0) {
            long r = row0 + warp * 8 + 2 * p;
            g_scores[r]     = read_mask(mask, r,     mmode) ? neg_inf() : (slo + b2s);
            g_scores[r + 1] = read_mask(mask, r + 1, mmode) ? neg_inf() : (shi + b2s);
        }
    }
}

// ============================================================================
// Kernel 2: per-slide bitonic sort (desc) of 8192 values; top100 = head,
// bottom100 (ascending) = tail of valid region.
// ============================================================================
__global__ __launch_bounds__(1024) void topk_kernel(float* __restrict__ out)
{
    __shared__ float s[8192];
    __shared__ int s_cnt;
    const int b = blockIdx.x;
    const int tid = threadIdx.x;

    if (tid == 0) s_cnt = 0;
    int cnt = 0;
    for (int i = tid; i < 8192; i += 1024) {
        float v = (i < NN) ? g_scores[b * NN + i] : neg_inf();
        s[i] = v;
        if (v > -3.0e38f) cnt++;
    }
#pragma unroll
    for (int o = 16; o > 0; o >>= 1) cnt += __shfl_xor_sync(0xffffffffu, cnt, o);
    __syncthreads();
    if ((tid & 31) == 0) atomicAdd(&s_cnt, cnt);

    for (int k = 2; k <= 8192; k <<= 1) {
        for (int j = k >> 1; j > 0; j >>= 1) {
            __syncthreads();
            for (int i = tid; i < 8192; i += 1024) {
                int l = i ^ j;
                if (l > i) {
                    float a = s[i], c = s[l];
                    bool descseg = ((i & k) == 0);
                    if (descseg ? (a < c) : (a > c)) { s[i] = c; s[l] = a; }
                }
            }
        }
    }
    __syncthreads();

    int valid = s_cnt;
    if (tid < NEXT) {
        float v = (tid < NTOP) ? s[tid] : s[valid - 1 - (tid - NTOP)];
        g_extreme[b * NEXT + tid] = v;
        out[BB + b * NEXT + tid] = v;
    }
}

// ============================================================================
// Kernel 3: tiny MLP 200 -> 128 -> 64 -> 1 per slide (fp32)
// ============================================================================
__global__ __launch_bounds__(128) void mlp_kernel(
    const float* __restrict__ Wm1, const float* __restrict__ bm1,
    const float* __restrict__ Wm2, const float* __restrict__ bm2,
    const float* __restrict__ Wm3, const float* __restrict__ bm3,
    float* __restrict__ out)
{
    __shared__ float ext[NEXT];
    __shared__ float g1[128];
    __shared__ float g2[64];
    const int b = blockIdx.x;
    const int tid = threadIdx.x;

    for (int i = tid; i < NEXT; i += 128) ext[i] = g_extreme[b * NEXT + i];
    __syncthreads();

    float a1 = bm1[tid];
    for (int i = 0; i < NEXT; i++) a1 += ext[i] * Wm1[i * 128 + tid];
    g1[tid] = sigmoidf_fast(a1);
    __syncthreads();

    if (tid < 64) {
        float a2 = bm2[tid];
        for (int i = 0; i < 128; i++) a2 += g1[i] * Wm2[i * 64 + tid];
        g2[tid] = sigmoidf_fast(a2);
    }
    __syncthreads();

    if (tid == 0) {
        float y = bm3[0];
        for (int i = 0; i < 64; i++) y += g2[i] * Wm3[i];
        out[b] = y;
    }
}

extern "C" void kernel_launch(void* const* d_in, const int* in_sizes, int n_in,
                              void* d_out, int out_size)
{
    const float* F    = (const float*)d_in[0];
    const void*  mask = d_in[1];
    const float* W1   = (const float*)d_in[2];
    const float* b1   = (const float*)d_in[3];
    const float* W2   = (const float*)d_in[4];
    const float* b2   = (const float*)d_in[5];
    const float* Wm1  = (const float*)d_in[6];
    const float* bm1  = (const float*)d_in[7];
    const float* Wm2  = (const float*)d_in[8];
    const float* bm2  = (const float*)d_in[9];
    const float* Wm3  = (const float*)d_in[10];
    const float* bm3  = (const float*)d_in[11];
    float* out = (float*)d_out;

    detect_mask_kernel<<<1, 256>>>((const unsigned*)mask);
    score_kernel<<<MROWS / TM, 256>>>(F, W1, b1, W2, b2, mask);
    topk_kernel<<<BB, 1024>>>(out);
    mlp_kernel<<<BB, 128>>>(Wm1, bm1, Wm2, bm2, Wm3, bm3, out);
}

// round 5
// speedup vs baseline: 2.6227x; 2.6227x over previous
#include <cuda_runtime.h>
#include <cstdint>

// Problem constants (fixed shapes for Chowder_17188459119037)
#define BB     16
#define NN     8000
#define DD     2048
#define HH     128
#define MROWS  (BB * NN)        // 128000
#define NTOP   100
#define NBOT   100
#define NEXT   (NTOP + NBOT)    // 200

#define TM     128              // rows per CTA
#define KT     16               // K elements per tile (2 k8 steps)
#define NTILES (DD / KT)        // 128
#define ASTRIDE 20              // A smem row stride in floats (conflict-free)

__device__ float g_scores[MROWS];
// W1^T pre-packed in mma fragment order: [tile][k8sub][ntile][lane][2], tf32-rounded
__device__ __align__(16) float g_W1P[DD * HH];
__device__ int   g_mask_mode;   // 0=int32, 1=uint8, 2=float32

__device__ __forceinline__ float neg_inf() { return __int_as_float(0xff800000); }
__device__ __forceinline__ float sigmoidf_fast(float x) {
    return 1.0f / (1.0f + __expf(-x));
}
__device__ __forceinline__ bool read_mask(const void* mask, size_t r, int mode) {
    if (mode == 1) return ((const unsigned char*)mask)[r] != 0;
    if (mode == 0) return ((const int*)mask)[r] != 0;
    return ((const float*)mask)[r] != 0.0f;
}
__device__ __forceinline__ uint32_t smem_u32(const void* p) {
    uint32_t a;
    asm("{ .reg .u64 t; cvta.to.shared.u64 t, %1; cvt.u32.u64 %0, t; }"
        : "=r"(a) : "l"(p));
    return a;
}
__device__ __forceinline__ uint32_t tf32u(float x) {  // rna round, bits out
    uint32_t r;
    asm("cvt.rna.tf32.f32 %0, %1;" : "=r"(r) : "f"(x));
    return r;
}
__device__ __forceinline__ float tf32f(float x) {
    return __uint_as_float(tf32u(x));
}
__device__ __forceinline__ void cp16(uint32_t s, const void* g) {
    asm volatile("cp.async.cg.shared.global [%0], [%1], 16;" :: "r"(s), "l"(g));
}
__device__ __forceinline__ void mma8(float* d, const uint32_t* a,
                                     uint32_t b0, uint32_t b1) {
    asm volatile(
        "mma.sync.aligned.m16n8k8.row.col.f32.tf32.tf32.f32 "
        "{%0,%1,%2,%3}, {%4,%5,%6,%7}, {%8,%9}, {%0,%1,%2,%3};"
        : "+f"(d[0]), "+f"(d[1]), "+f"(d[2]), "+f"(d[3])
        : "r"(a[0]), "r"(a[1]), "r"(a[2]), "r"(a[3]), "r"(b0), "r"(b1));
}

// ============================================================================
// Kernel 0: detect mask dtype (scans first 32000 dwords — in-bounds for u8,
// i32 and f32 interpretations). 1.0f pattern -> f32; any dword>1 -> packed u8.
// ============================================================================
__global__ void detect_mask_kernel(const unsigned* __restrict__ m) {
    __shared__ int s_f32, s_u8;
    if (threadIdx.x == 0) { s_f32 = 0; s_u8 = 0; }
    __syncthreads();
    int f32 = 0, u8 = 0;
    for (int i = threadIdx.x; i < 32000; i += 256) {
        unsigned v = m[i];
        if (v == 0x3F800000u) f32 = 1;
        else if (v > 1u)      u8 = 1;
    }
    if (f32) s_f32 = 1;
    if (u8)  s_u8 = 1;
    __syncthreads();
    if (threadIdx.x == 0) g_mask_mode = s_f32 ? 2 : (s_u8 ? 1 : 0);
}

// ============================================================================
// Kernel 0b: pack W1 [2048,128] into fragment-ordered, tf32-rounded g_W1P.
// Pair i: lane=i&31, ntile=(i>>5)&15, sub=(i>>9)&1, tile=i>>10.
// n = ntile*8 + lane>>2 ; k = tile*16 + sub*8 + (lane&3); stores {B[n][k],B[n][k+4]}
// ============================================================================
__global__ void prep_b_kernel(const float* __restrict__ W1) {
    int i = blockIdx.x * 256 + threadIdx.x;      // 0..131071
    int lane = i & 31, nt = (i >> 5) & 15, sub = (i >> 9) & 1, tile = i >> 10;
    int n = nt * 8 + (lane >> 2);
    int k = tile * 16 + sub * 8 + (lane & 3);
    float v0 = tf32f(W1[(size_t)k * HH + n]);
    float v1 = tf32f(W1[(size_t)(k + 4) * HH + n]);
    ((float2*)g_W1P)[i] = make_float2(v0, v1);
}

// ============================================================================
// Kernel 1: TF32 mma.sync GEMM + fused sigmoid/W2 epilogue -> g_scores
// ============================================================================
__device__ __forceinline__ void load_tile(float* Asm, float* Bsm,
                                          const float* __restrict__ F,
                                          size_t row_base, int kt, int tid)
{
#pragma unroll
    for (int h = 0; h < 2; h++) {                // A: 512 float4
        int i = tid + h * 256;
        int row = i >> 2, quad = i & 3;
        cp16(smem_u32(Asm + row * ASTRIDE + quad * 4),
             F + (row_base + row) * DD + kt * 16 + quad * 4);
    }
    const float* bsrc = g_W1P + (size_t)kt * 2048;
#pragma unroll
    for (int h = 0; h < 2; h++) {                // B: 512 float4 (contiguous)
        int i = tid + h * 256;
        cp16(smem_u32(Bsm + i * 4), bsrc + i * 4);
    }
}

__global__ __launch_bounds__(256, 2) void score_kernel(
    const float* __restrict__ F,
    const float* __restrict__ b1,
    const float* __restrict__ W2,
    const float* __restrict__ b2,
    const void*  __restrict__ mask)
{
    __shared__ float As[2][TM * ASTRIDE];   // 2 x 10240 B
    __shared__ float Bs[2][2048];           // 2 x 8192 B
    __shared__ float part[2][TM];

    const int tid  = threadIdx.x;
    const int lane = tid & 31;
    const int wid  = tid >> 5;
    const int mw   = wid & 3;     // 4 M-warps x 32 rows
    const int nw   = wid >> 2;    // 2 N-warps x 64 cols
    const size_t row_base = (size_t)blockIdx.x * TM;

    float acc[2][8][4];
#pragma unroll
    for (int mt = 0; mt < 2; mt++)
#pragma unroll
        for (int j = 0; j < 8; j++)
#pragma unroll
            for (int e = 0; e < 4; e++) acc[mt][j][e] = 0.f;

    load_tile(As[0], Bs[0], F, row_base, 0, tid);
    asm volatile("cp.async.commit_group;" ::: "memory");

    for (int t = 0; t < NTILES; t++) {
        const int buf = t & 1;
        if (t + 1 < NTILES) {
            load_tile(As[buf ^ 1], Bs[buf ^ 1], F, row_base, t + 1, tid);
            asm volatile("cp.async.commit_group;" ::: "memory");
            asm volatile("cp.async.wait_group 1;" ::: "memory");
        } else {
            asm volatile("cp.async.wait_group 0;" ::: "memory");
        }
        __syncthreads();

        const float* A = As[buf];
        const float* Bm = Bs[buf];
#pragma unroll
        for (int s = 0; s < 2; s++) {
            uint32_t a[2][4];
            const int c0 = s * 8 + (lane & 3);
            const int r0 = mw * 32 + (lane >> 2);
#pragma unroll
            for (int mt = 0; mt < 2; mt++) {
                const int rb = r0 + mt * 16;
                a[mt][0] = tf32u(A[rb * ASTRIDE + c0]);
                a[mt][1] = tf32u(A[(rb + 8) * ASTRIDE + c0]);
                a[mt][2] = tf32u(A[rb * ASTRIDE + c0 + 4]);
                a[mt][3] = tf32u(A[(rb + 8) * ASTRIDE + c0 + 4]);
            }
#pragma unroll
            for (int j = 0; j < 8; j++) {
                float2 bv = *(const float2*)&Bm[s * 1024 + (nw * 8 + j) * 64 + lane * 2];
                uint32_t b0 = __float_as_uint(bv.x);
                uint32_t b1r = __float_as_uint(bv.y);
                mma8(acc[0][j], a[0], b0, b1r);
                mma8(acc[1][j], a[1], b0, b1r);
            }
        }
        __syncthreads();
    }

    // Epilogue: per-row dot( W2, sigmoid(acc + b1) ), quad-reduce, combine N-halves
    const float b2s = b2[0];
    const int mmode = g_mask_mode;
#pragma unroll
    for (int mt = 0; mt < 2; mt++) {
        float p0 = 0.f, p1 = 0.f;
#pragma unroll
        for (int j = 0; j < 8; j++) {
            const int cb = nw * 64 + j * 8 + 2 * (lane & 3);
            float w0 = W2[cb], w1 = W2[cb + 1];
            float v0 = b1[cb], v1 = b1[cb + 1];
            p0 += w0 * sigmoidf_fast(acc[mt][j][0] + v0)
                + w1 * sigmoidf_fast(acc[mt][j][1] + v1);
            p1 += w0 * sigmoidf_fast(acc[mt][j][2] + v0)
                + w1 * sigmoidf_fast(acc[mt][j][3] + v1);
        }
        p0 += __shfl_xor_sync(0xffffffffu, p0, 1);
        p0 += __shfl_xor_sync(0xffffffffu, p0, 2);
        p1 += __shfl_xor_sync(0xffffffffu, p1, 1);
        p1 += __shfl_xor_sync(0xffffffffu, p1, 2);
        if ((lane & 3) == 0) {
            int lr = mw * 32 + mt * 16 + (lane >> 2);
            part[nw][lr]     = p0;
            part[nw][lr + 8] = p1;
        }
    }
    __syncthreads();
    if (tid < TM) {
        size_t r = row_base + tid;
        float sc = part[0][tid] + part[1][tid] + b2s;
        g_scores[r] = read_mask(mask, r, mmode) ? neg_inf() : sc;
    }
}

// ============================================================================
// Kernel 2: per-slide bitonic sort (desc) + extreme extraction + tiny MLP
// ============================================================================
__global__ __launch_bounds__(1024) void topk_mlp_kernel(
    const float* __restrict__ Wm1, const float* __restrict__ bm1,
    const float* __restrict__ Wm2, const float* __restrict__ bm2,
    const float* __restrict__ Wm3, const float* __restrict__ bm3,
    float* __restrict__ out)
{
    __shared__ float s[8192];
    __shared__ int s_cnt;
    __shared__ float ext[NEXT];
    __shared__ float g1[128];
    __shared__ float g2[64];
    const int b = blockIdx.x;
    const int tid = threadIdx.x;

    if (tid == 0) s_cnt = 0;
    int cnt = 0;
    for (int i = tid; i < 8192; i += 1024) {
        float v = (i < NN) ? g_scores[b * NN + i] : neg_inf();
        s[i] = v;
        if (v > -3.0e38f) cnt++;
    }
#pragma unroll
    for (int o = 16; o > 0; o >>= 1) cnt += __shfl_xor_sync(0xffffffffu, cnt, o);
    __syncthreads();
    if ((tid & 31) == 0) atomicAdd(&s_cnt, cnt);

    for (int k = 2; k <= 8192; k <<= 1) {
        for (int j = k >> 1; j > 0; j >>= 1) {
            __syncthreads();
            for (int i = tid; i < 8192; i += 1024) {
                int l = i ^ j;
                if (l > i) {
                    float a = s[i], c = s[l];
                    bool descseg = ((i & k) == 0);
                    if (descseg ? (a < c) : (a > c)) { s[i] = c; s[l] = a; }
                }
            }
        }
    }
    __syncthreads();

    const int valid = s_cnt;
    if (tid < NEXT) {
        float v = (tid < NTOP) ? s[tid] : s[valid - 1 - (tid - NTOP)];
        ext[tid] = v;
        out[BB + b * NEXT + tid] = v;
    }
    __syncthreads();

    if (tid < 128) {
        float a1 = bm1[tid];
        for (int i = 0; i < NEXT; i++) a1 += ext[i] * Wm1[i * 128 + tid];
        g1[tid] = sigmoidf_fast(a1);
    }
    __syncthreads();
    if (tid < 64) {
        float a2 = bm2[tid];
        for (int i = 0; i < 128; i++) a2 += g1[i] * Wm2[i * 64 + tid];
        g2[tid] = sigmoidf_fast(a2);
    }
    __syncthreads();
    if (tid == 0) {
        float y = bm3[0];
        for (int i = 0; i < 64; i++) y += g2[i] * Wm3[i];
        out[b] = y;
    }
}

extern "C" void kernel_launch(void* const* d_in, const int* in_sizes, int n_in,
                              void* d_out, int out_size)
{
    const float* F    = (const float*)d_in[0];
    const void*  mask = d_in[1];
    const float* W1   = (const float*)d_in[2];
    const float* b1   = (const float*)d_in[3];
    const float* W2   = (const float*)d_in[4];
    const float* b2   = (const float*)d_in[5];
    const float* Wm1  = (const float*)d_in[6];
    const float* bm1  = (const float*)d_in[7];
    const float* Wm2  = (const float*)d_in[8];
    const float* bm2  = (const float*)d_in[9];
    const float* Wm3  = (const float*)d_in[10];
    const float* bm3  = (const float*)d_in[11];
    float* out = (float*)d_out;

    detect_mask_kernel<<<1, 256>>>((const unsigned*)mask);
    prep_b_kernel<<<512, 256>>>(W1);
    score_kernel<<<MROWS / TM, 256>>>(F, b1, W2, b2, mask);
    topk_mlp_kernel<<<BB, 1024>>>(Wm1, bm1, Wm2, bm2, Wm3, bm3, out);
}

// round 6
// speedup vs baseline: 3.7508x; 1.4302x over previous
#include <cuda_runtime.h>
#include <cuda_fp16.h>
#include <cstdint>

// Problem constants (fixed shapes for Chowder_17188459119037)
#define BB     16
#define NN     8000
#define DD     2048
#define HH     128
#define MROWS  (BB * NN)        // 128000
#define NTOP   100
#define NBOT   100
#define NEXT   (NTOP + NBOT)    // 200

#define TM      128             // rows per CTA
#define KT      16              // K elements per tile (one m16n8k16 step)
#define NTILES  (DD / KT)       // 128
#define ASTRIDE 24              // A smem row stride in floats (LDS.64 conflict-free)
#define SEGS    8
#define SEGLEN  (NN / SEGS)     // 1000

__device__ float g_scores[MROWS];
// W1 packed fp16 fragment order: [tile][ntile][lane][2] uint32 (f16x2)
__device__ __align__(16) unsigned g_W1H[NTILES * 16 * 32 * 2];
__device__ float g_ctop[BB * SEGS * NTOP];
__device__ float g_cbot[BB * SEGS * NBOT];
__device__ int   g_mask_mode;   // 0=int32, 1=uint8, 2=float32

__device__ __forceinline__ float neg_inf() { return __int_as_float(0xff800000); }
__device__ __forceinline__ float pos_inf() { return __int_as_float(0x7f800000); }
__device__ __forceinline__ float sigmoidf_fast(float x) {
    return 1.0f / (1.0f + __expf(-x));
}
__device__ __forceinline__ bool read_mask(const void* mask, size_t r, int mode) {
    if (mode == 1) return ((const unsigned char*)mask)[r] != 0;
    if (mode == 0) return ((const int*)mask)[r] != 0;
    return ((const float*)mask)[r] != 0.0f;
}
__device__ __forceinline__ uint32_t smem_u32(const void* p) {
    uint32_t a;
    asm("{ .reg .u64 t; cvta.to.shared.u64 t, %1; cvt.u32.u64 %0, t; }"
        : "=r"(a) : "l"(p));
    return a;
}
__device__ __forceinline__ void cp16(uint32_t s, const void* g) {
    asm volatile("cp.async.cg.shared.global [%0], [%1], 16;" :: "r"(s), "l"(g));
}
// pack float2 -> f16x2 (lo = x, hi = y)
__device__ __forceinline__ uint32_t f16x2(float lo, float hi) {
    uint32_t r;
    asm("cvt.rn.f16x2.f32 %0, %1, %2;" : "=r"(r) : "f"(hi), "f"(lo));
    return r;
}
__device__ __forceinline__ void mma16(float* d, const uint32_t* a,
                                      uint32_t b0, uint32_t b1) {
    asm volatile(
        "mma.sync.aligned.m16n8k16.row.col.f32.f16.f16.f32 "
        "{%0,%1,%2,%3}, {%4,%5,%6,%7}, {%8,%9}, {%0,%1,%2,%3};"
        : "+f"(d[0]), "+f"(d[1]), "+f"(d[2]), "+f"(d[3])
        : "r"(a[0]), "r"(a[1]), "r"(a[2]), "r"(a[3]), "r"(b0), "r"(b1));
}

// ============================================================================
// Kernel 0: detect mask dtype (scans first 32000 dwords — in-bounds for u8,
// i32 and f32 interpretations). 1.0f pattern -> f32; any dword>1 -> packed u8.
// ============================================================================
__global__ void detect_mask_kernel(const unsigned* __restrict__ m) {
    __shared__ int s_f32, s_u8;
    if (threadIdx.x == 0) { s_f32 = 0; s_u8 = 0; }
    __syncthreads();
    int f32 = 0, u8 = 0;
    for (int i = threadIdx.x; i < 32000; i += 256) {
        unsigned v = m[i];
        if (v == 0x3F800000u) f32 = 1;
        else if (v > 1u)      u8 = 1;
    }
    if (f32) s_f32 = 1;
    if (u8)  s_u8 = 1;
    __syncthreads();
    if (threadIdx.x == 0) g_mask_mode = s_f32 ? 2 : (s_u8 ? 1 : 0);
}

// ============================================================================
// Kernel 0b: pack W1 [2048,128] -> g_W1H fp16 fragment order.
// i = (tile, ntile, lane): n = ntile*8 + lane>>2; k = tile*16 + 2*(lane&3)
// reg0 = {W1[k][n], W1[k+1][n]}, reg1 = {W1[k+8][n], W1[k+9][n]}
// ============================================================================
__global__ void prep_w1h_kernel(const float* __restrict__ W1) {
    int i = blockIdx.x * 256 + threadIdx.x;   // 0..65535
    int lane = i & 31, nt = (i >> 5) & 15, tile = i >> 9;
    int n = nt * 8 + (lane >> 2);
    int k = tile * 16 + 2 * (lane & 3);
    uint32_t r0 = f16x2(W1[(size_t)k * HH + n],       W1[(size_t)(k + 1) * HH + n]);
    uint32_t r1 = f16x2(W1[(size_t)(k + 8) * HH + n], W1[(size_t)(k + 9) * HH + n]);
    ((uint2*)g_W1H)[i] = make_uint2(r0, r1);
}

// ============================================================================
// Kernel 1: fp16 mma.sync GEMM (fp32 accum) + fused sigmoid/W2 epilogue
// ============================================================================
__device__ __forceinline__ void load_tile(float* Asm, unsigned* Bsm,
                                          const float* __restrict__ F,
                                          size_t row_base, int kt, int tid)
{
#pragma unroll
    for (int h = 0; h < 2; h++) {                // A: 512 x 16B
        int i = tid + h * 256;
        int row = i >> 2, quad = i & 3;
        cp16(smem_u32(Asm + row * ASTRIDE + quad * 4),
             F + (row_base + row) * DD + kt * 16 + quad * 4);
    }
    // B: 256 x 16B (4 KB contiguous fragment-ordered tile)
    cp16(smem_u32(Bsm + tid * 4), g_W1H + (size_t)kt * 1024 + tid * 4);
}

__global__ __launch_bounds__(256, 2) void score_kernel(
    const float* __restrict__ F,
    const float* __restrict__ b1,
    const float* __restrict__ W2,
    const float* __restrict__ b2,
    const void*  __restrict__ mask)
{
    __shared__ float    As[2][TM * ASTRIDE];   // 2 x 12 KB
    __shared__ unsigned Bs[2][1024];           // 2 x 4 KB
    __shared__ float    part[2][TM];

    const int tid  = threadIdx.x;
    const int lane = tid & 31;
    const int wid  = tid >> 5;
    const int mw   = wid & 3;     // 4 M-warps x 32 rows
    const int nw   = wid >> 2;    // 2 N-warps x 64 cols
    const size_t row_base = (size_t)blockIdx.x * TM;

    float acc[2][8][4];
#pragma unroll
    for (int mt = 0; mt < 2; mt++)
#pragma unroll
        for (int j = 0; j < 8; j++)
#pragma unroll
            for (int e = 0; e < 4; e++) acc[mt][j][e] = 0.f;

    load_tile(As[0], Bs[0], F, row_base, 0, tid);
    asm volatile("cp.async.commit_group;" ::: "memory");

    const int k2 = 2 * (lane & 3);
    const int r0 = mw * 32 + (lane >> 2);

    for (int t = 0; t < NTILES; t++) {
        const int buf = t & 1;
        if (t + 1 < NTILES) {
            load_tile(As[buf ^ 1], Bs[buf ^ 1], F, row_base, t + 1, tid);
            asm volatile("cp.async.commit_group;" ::: "memory");
            asm volatile("cp.async.wait_group 1;" ::: "memory");
        } else {
            asm volatile("cp.async.wait_group 0;" ::: "memory");
        }
        __syncthreads();

        const float* A = As[buf];
        const unsigned* Bm = Bs[buf];

        uint32_t a[2][4];
#pragma unroll
        for (int mt = 0; mt < 2; mt++) {
            const int rb = r0 + mt * 16;
            float2 v0 = *(const float2*)&A[rb * ASTRIDE + k2];
            float2 v1 = *(const float2*)&A[(rb + 8) * ASTRIDE + k2];
            float2 v2 = *(const float2*)&A[rb * ASTRIDE + k2 + 8];
            float2 v3 = *(const float2*)&A[(rb + 8) * ASTRIDE + k2 + 8];
            a[mt][0] = f16x2(v0.x, v0.y);
            a[mt][1] = f16x2(v1.x, v1.y);
            a[mt][2] = f16x2(v2.x, v2.y);
            a[mt][3] = f16x2(v3.x, v3.y);
        }
#pragma unroll
        for (int j = 0; j < 8; j++) {
            uint2 bv = *(const uint2*)&Bm[((nw * 8 + j) * 32 + lane) * 2];
            mma16(acc[0][j], a[0], bv.x, bv.y);
            mma16(acc[1][j], a[1], bv.x, bv.y);
        }
        __syncthreads();
    }

    // Epilogue: per-row dot( W2, sigmoid(acc + b1) ), quad-reduce, combine halves
    const float b2s = b2[0];
    const int mmode = g_mask_mode;
#pragma unroll
    for (int mt = 0; mt < 2; mt++) {
        float p0 = 0.f, p1 = 0.f;
#pragma unroll
        for (int j = 0; j < 8; j++) {
            const int cb = nw * 64 + j * 8 + k2;
            float w0 = W2[cb], w1 = W2[cb + 1];
            float v0 = b1[cb], v1 = b1[cb + 1];
            p0 += w0 * sigmoidf_fast(acc[mt][j][0] + v0)
                + w1 * sigmoidf_fast(acc[mt][j][1] + v1);
            p1 += w0 * sigmoidf_fast(acc[mt][j][2] + v0)
                + w1 * sigmoidf_fast(acc[mt][j][3] + v1);
        }
        p0 += __shfl_xor_sync(0xffffffffu, p0, 1);
        p0 += __shfl_xor_sync(0xffffffffu, p0, 2);
        p1 += __shfl_xor_sync(0xffffffffu, p1, 1);
        p1 += __shfl_xor_sync(0xffffffffu, p1, 2);
        if ((lane & 3) == 0) {
            int lr = mw * 32 + mt * 16 + (lane >> 2);
            part[nw][lr]     = p0;
            part[nw][lr + 8] = p1;
        }
    }
    __syncthreads();
    if (tid < TM) {
        size_t r = row_base + tid;
        float sc = part[0][tid] + part[1][tid] + b2s;
        g_scores[r] = read_mask(mask, r, mmode) ? neg_inf() : sc;
    }
}

// ---------------- bitonic sort helper (1024 elems, 512 threads) -------------
__device__ __forceinline__ void bitonic1024(float* s, int tid, bool desc) {
    for (int k = 2; k <= 1024; k <<= 1) {
        for (int j = k >> 1; j > 0; j >>= 1) {
            __syncthreads();
#pragma unroll 2
            for (int i = tid; i < 1024; i += 512) {
                int l = i ^ j;
                if (l > i) {
                    float a = s[i], c = s[l];
                    bool seg = ((i & k) == 0) == desc;   // true => want a >= c
                    if (seg ? (a < c) : (a > c)) { s[i] = c; s[l] = a; }
                }
            }
        }
    }
    __syncthreads();
}

// ============================================================================
// Kernel 2a: per-(slide,segment) sort of 1000 scores -> top100 + bottom100
// candidates. Grid = 16*8 = 128 blocks x 512 threads.
// ============================================================================
__global__ __launch_bounds__(512) void seg_topk_kernel()
{
    __shared__ float s[1024];
    __shared__ int s_cnt;
    const int blk = blockIdx.x;
    const int b = blk >> 3, seg = blk & 7;
    const int tid = threadIdx.x;
    const size_t base = (size_t)b * NN + seg * SEGLEN;

    if (tid == 0) s_cnt = 0;
    __syncthreads();
    int cnt = 0;
#pragma unroll 2
    for (int i = tid; i < 1024; i += 512) {
        float v = (i < SEGLEN) ? g_scores[base + i] : neg_inf();
        s[i] = v;
        if (v > -3.0e38f) cnt++;
    }
#pragma unroll
    for (int o = 16; o > 0; o >>= 1) cnt += __shfl_xor_sync(0xffffffffu, cnt, o);
    if ((tid & 31) == 0) atomicAdd(&s_cnt, cnt);

    bitonic1024(s, tid, true);   // descending

    const int valid = s_cnt;
    if (tid < NTOP) g_ctop[blk * NTOP + tid] = s[tid];
    if (tid >= 256 && tid < 256 + NBOT) {
        int t = tid - 256;
        int j = valid - 1 - t;
        g_cbot[blk * NBOT + t] = (j >= 0) ? s[j] : pos_inf();
    }
}

// ============================================================================
// Kernel 2b: merge 800 top / 800 bottom candidates per slide, extract extreme,
// run tiny MLP. Grid = 16 blocks x 512 threads.
// ============================================================================
__global__ __launch_bounds__(512) void merge_mlp_kernel(
    const float* __restrict__ Wm1, const float* __restrict__ bm1,
    const float* __restrict__ Wm2, const float* __restrict__ bm2,
    const float* __restrict__ Wm3, const float* __restrict__ bm3,
    float* __restrict__ out)
{
    __shared__ float c[1024];
    __shared__ float ext[NEXT];
    __shared__ float g1[128];
    __shared__ float g2[64];
    const int b = blockIdx.x;
    const int tid = threadIdx.x;

    // ---- top: 800 candidates, sort desc, take 100 ----
#pragma unroll 2
    for (int i = tid; i < 1024; i += 512)
        c[i] = (i < SEGS * NTOP) ? g_ctop[b * SEGS * NTOP + i] : neg_inf();
    bitonic1024(c, tid, true);
    if (tid < NTOP) {
        ext[tid] = c[tid];
        out[BB + b * NEXT + tid] = c[tid];
    }
    __syncthreads();

    // ---- bottom: 800 candidates, sort asc, take 100 ----
#pragma unroll 2
    for (int i = tid; i < 1024; i += 512)
        c[i] = (i < SEGS * NBOT) ? g_cbot[b * SEGS * NBOT + i] : pos_inf();
    bitonic1024(c, tid, false);
    if (tid < NBOT) {
        ext[NTOP + tid] = c[tid];
        out[BB + b * NEXT + NTOP + tid] = c[tid];
    }
    __syncthreads();

    // ---- MLP 200 -> 128 -> 64 -> 1 ----
    if (tid < 128) {
        float a1 = bm1[tid];
        for (int i = 0; i < NEXT; i++) a1 += ext[i] * Wm1[i * 128 + tid];
        g1[tid] = sigmoidf_fast(a1);
    }
    __syncthreads();
    if (tid < 64) {
        float a2 = bm2[tid];
        for (int i = 0; i < 128; i++) a2 += g1[i] * Wm2[i * 64 + tid];
        g2[tid] = sigmoidf_fast(a2);
    }
    __syncthreads();
    if (tid == 0) {
        float y = bm3[0];
        for (int i = 0; i < 64; i++) y += g2[i] * Wm3[i];
        out[b] = y;
    }
}

extern "C" void kernel_launch(void* const* d_in, const int* in_sizes, int n_in,
                              void* d_out, int out_size)
{
    const float* F    = (const float*)d_in[0];
    const void*  mask = d_in[1];
    const float* W1   = (const float*)d_in[2];
    const float* b1   = (const float*)d_in[3];
    const float* W2   = (const float*)d_in[4];
    const float* b2   = (const float*)d_in[5];
    const float* Wm1  = (const float*)d_in[6];
    const float* bm1  = (const float*)d_in[7];
    const float* Wm2  = (const float*)d_in[8];
    const float* bm2  = (const float*)d_in[9];
    const float* Wm3  = (const float*)d_in[10];
    const float* bm3  = (const float*)d_in[11];
    float* out = (float*)d_out;

    detect_mask_kernel<<<1, 256>>>((const unsigned*)mask);
    prep_w1h_kernel<<<256, 256>>>(W1);
    score_kernel<<<MROWS / TM, 256>>>(F, b1, W2, b2, mask);
    seg_topk_kernel<<<BB * SEGS, 512>>>();
    merge_mlp_kernel<<<BB, 512>>>(Wm1, bm1, Wm2, bm2, Wm3, bm3, out);
}